// round 1
// baseline (speedup 1.0000x reference)
#include <cuda_runtime.h>

#define N_NODES_MAX 50000
#define IN_C  128
#define HID_C 64
#define OUT_C 32

// ---------------- scratch (no allocations allowed) ----------------
__device__ int   g_deg [N_NODES_MAX];
__device__ float g_dinv[N_NODES_MAX];
__device__ __align__(16) float g_xw1 [N_NODES_MAX * HID_C];  // x @ W1
__device__ __align__(16) float g_agg1[N_NODES_MAX * HID_C];  // layer1 aggregation
__device__ __align__(16) float g_hw2 [N_NODES_MAX * OUT_C];  // relu(h) @ W2
__device__ __align__(16) float g_agg2[N_NODES_MAX * OUT_C];  // layer2 aggregation = z

// ---------------- degree / norm ----------------
__global__ void k_deg_init(int n) {
    int i = blockIdx.x * blockDim.x + threadIdx.x;
    if (i < n) g_deg[i] = 1;  // self loop
}
__global__ void k_deg(const int* __restrict__ dst, int E) {
    int e = blockIdx.x * blockDim.x + threadIdx.x;
    if (e < E) atomicAdd(&g_deg[dst[e]], 1);
}
__global__ void k_dinv(int n) {
    int i = blockIdx.x * blockDim.x + threadIdx.x;
    if (i < n) g_dinv[i] = rsqrtf((float)g_deg[i]);
}

// ---------------- GEMM1: xw1 = x@W1 ; agg1 init = xw1*dinv^2 + b1 ----------------
// 256 threads, 16 rows per block. Each warp: 2 rows; lane covers cols (lane, lane+32).
__global__ __launch_bounds__(256) void k_gemm1(const float* __restrict__ x,
                                               const float* __restrict__ W1,
                                               const float* __restrict__ b1, int n) {
    __shared__ float sWt[HID_C * 132];   // transposed, padded: sWt[c*132 + k]
    __shared__ float sx[16 * IN_C];
    int tid = threadIdx.x;
    for (int i = tid; i < IN_C * HID_C; i += 256) {
        int k = i >> 6, c = i & 63;
        sWt[c * 132 + k] = W1[i];
    }
    int row0 = blockIdx.x * 16;
    for (int i = tid; i < 16 * IN_C; i += 256) {
        int r = row0 + (i >> 7);
        sx[i] = (r < n) ? x[(size_t)r * IN_C + (i & 127)] : 0.f;
    }
    __syncthreads();

    int warp = tid >> 5, lane = tid & 31;
    int r0 = warp * 2, r1 = r0 + 1;
    float a00 = 0.f, a01 = 0.f, a10 = 0.f, a11 = 0.f;
    const float4* sx4 = (const float4*)sx;
    const float4* w0p = (const float4*)(sWt + lane * 132);          // 132*4=528 = 33*16: aligned
    const float4* w1p = (const float4*)(sWt + (lane + 32) * 132);
#pragma unroll
    for (int kk = 0; kk < IN_C / 4; kk++) {
        float4 xa = sx4[r0 * 32 + kk];
        float4 xb = sx4[r1 * 32 + kk];
        float4 w0 = w0p[kk];
        float4 w1 = w1p[kk];
        a00 = fmaf(xa.x, w0.x, a00); a00 = fmaf(xa.y, w0.y, a00);
        a00 = fmaf(xa.z, w0.z, a00); a00 = fmaf(xa.w, w0.w, a00);
        a01 = fmaf(xa.x, w1.x, a01); a01 = fmaf(xa.y, w1.y, a01);
        a01 = fmaf(xa.z, w1.z, a01); a01 = fmaf(xa.w, w1.w, a01);
        a10 = fmaf(xb.x, w0.x, a10); a10 = fmaf(xb.y, w0.y, a10);
        a10 = fmaf(xb.z, w0.z, a10); a10 = fmaf(xb.w, w0.w, a10);
        a11 = fmaf(xb.x, w1.x, a11); a11 = fmaf(xb.y, w1.y, a11);
        a11 = fmaf(xb.z, w1.z, a11); a11 = fmaf(xb.w, w1.w, a11);
    }
    int gr0 = row0 + r0, gr1 = row0 + r1;
    float bl = b1[lane], bh = b1[lane + 32];
    if (gr0 < n) {
        float di = g_dinv[gr0], s = di * di;
        g_xw1 [(size_t)gr0 * HID_C + lane]      = a00;
        g_xw1 [(size_t)gr0 * HID_C + lane + 32] = a01;
        g_agg1[(size_t)gr0 * HID_C + lane]      = fmaf(a00, s, bl);
        g_agg1[(size_t)gr0 * HID_C + lane + 32] = fmaf(a01, s, bh);
    }
    if (gr1 < n) {
        float di = g_dinv[gr1], s = di * di;
        g_xw1 [(size_t)gr1 * HID_C + lane]      = a10;
        g_xw1 [(size_t)gr1 * HID_C + lane + 32] = a11;
        g_agg1[(size_t)gr1 * HID_C + lane]      = fmaf(a10, s, bl);
        g_agg1[(size_t)gr1 * HID_C + lane + 32] = fmaf(a11, s, bh);
    }
}

// ---------------- edge scatter: agg[d] += feat[s] * dinv[s]*dinv[d] ----------------
// C floats per row, C/4 threads per edge, vector red.global.add.v4.f32.
template <int C>
__global__ __launch_bounds__(256) void k_scatter(const int* __restrict__ src,
                                                 const int* __restrict__ dst, int E) {
    const int TPE = C / 4;
    const float* feat = (C == HID_C) ? g_xw1  : g_hw2;
    float*       agg  = (C == HID_C) ? g_agg1 : g_agg2;
    int g = blockIdx.x * blockDim.x + threadIdx.x;
    int e = g / TPE;
    int t = g % TPE;
    bool valid = (e < E);
    if (!valid) e = 0;
    int a = 0, d = 0; float norm = 0.f;
    if (t == 0) {
        a = src[e]; d = dst[e];
        norm = g_dinv[a] * g_dinv[d];
    }
    a    = __shfl_sync(0xffffffffu, a, 0, TPE);
    d    = __shfl_sync(0xffffffffu, d, 0, TPE);
    norm = __shfl_sync(0xffffffffu, norm, 0, TPE);
    float4 v = *(const float4*)(feat + (size_t)a * C + t * 4);
    v.x *= norm; v.y *= norm; v.z *= norm; v.w *= norm;
    if (valid) {
        float* p = agg + (size_t)d * C + t * 4;
        asm volatile("red.global.add.v4.f32 [%0], {%1,%2,%3,%4};"
                     :: "l"(p), "f"(v.x), "f"(v.y), "f"(v.z), "f"(v.w) : "memory");
    }
}

// ---------------- layer2: h = relu(agg1); hw2 = h@W2 ; agg2 init = hw2*dinv^2 + b2 ----------------
// 256 threads, 8 nodes per block (one warp each); lane = output col.
__global__ __launch_bounds__(256) void k_layer2(const float* __restrict__ W2,
                                                const float* __restrict__ b2, int n) {
    __shared__ float sWt[OUT_C * 68];  // sWt[c*68 + k], 68*4=272=17*16: aligned
    __shared__ float sh[8 * HID_C];
    int tid = threadIdx.x;
    for (int i = tid; i < HID_C * OUT_C; i += 256) {
        int k = i >> 5, c = i & 31;
        sWt[c * 68 + k] = W2[i];
    }
    __syncthreads();
    int warp = tid >> 5, lane = tid & 31;
    int node = blockIdx.x * 8 + warp;
    if (node >= n) return;
    float2 hv = *(const float2*)(g_agg1 + (size_t)node * HID_C + lane * 2);
    hv.x = fmaxf(hv.x, 0.f);
    hv.y = fmaxf(hv.y, 0.f);
    *(float2*)(sh + warp * HID_C + lane * 2) = hv;
    __syncwarp();
    float acc = 0.f;
    const float4* sh4 = (const float4*)(sh + warp * HID_C);
    const float4* w4  = (const float4*)(sWt + lane * 68);
#pragma unroll
    for (int kk = 0; kk < HID_C / 4; kk++) {
        float4 h4 = sh4[kk];
        float4 w  = w4[kk];
        acc = fmaf(h4.x, w.x, acc); acc = fmaf(h4.y, w.y, acc);
        acc = fmaf(h4.z, w.z, acc); acc = fmaf(h4.w, w.w, acc);
    }
    float di = g_dinv[node], s = di * di;
    g_hw2 [(size_t)node * OUT_C + lane] = acc;
    g_agg2[(size_t)node * OUT_C + lane] = fmaf(acc, s, b2[lane]);
}

// ---------------- decode: logits[e] = dot(z[a], z[b]) ----------------
// 8 lanes per edge, float4 gathers (full 128B line per row), segmented shuffle reduce.
__global__ __launch_bounds__(256) void k_decode(const int* __restrict__ de, int E,
                                                float* __restrict__ out) {
    int g = blockIdx.x * blockDim.x + threadIdx.x;
    int e = g >> 3, t = g & 7;
    bool valid = (e < E);
    if (!valid) e = 0;
    int a = 0, b = 0;
    if (t == 0) { a = de[e]; b = de[E + e]; }
    a = __shfl_sync(0xffffffffu, a, 0, 8);
    b = __shfl_sync(0xffffffffu, b, 0, 8);
    float4 za = *(const float4*)(g_agg2 + (size_t)a * OUT_C + t * 4);
    float4 zb = *(const float4*)(g_agg2 + (size_t)b * OUT_C + t * 4);
    float p = za.x * zb.x + za.y * zb.y + za.z * zb.z + za.w * zb.w;
    p += __shfl_down_sync(0xffffffffu, p, 4, 8);
    p += __shfl_down_sync(0xffffffffu, p, 2, 8);
    p += __shfl_down_sync(0xffffffffu, p, 1, 8);
    if (valid && t == 0) out[e] = p;
}

// ---------------- launch ----------------
extern "C" void kernel_launch(void* const* d_in, const int* in_sizes, int n_in,
                              void* d_out, int out_size) {
    const float* x  = (const float*)d_in[0];
    const float* W1 = (const float*)d_in[1];
    const float* b1 = (const float*)d_in[2];
    const float* W2 = (const float*)d_in[3];
    const float* b2 = (const float*)d_in[4];
    const int*   ei = (const int*)d_in[5];
    const int*   de = (const int*)d_in[6];

    int N  = in_sizes[0] / IN_C;
    int E  = in_sizes[5] / 2;
    int Ed = in_sizes[6] / 2;
    const int* src = ei;
    const int* dst = ei + E;
    float* out = (float*)d_out;

    k_deg_init<<<(N + 255) / 256, 256>>>(N);
    k_deg<<<(E + 255) / 256, 256>>>(dst, E);
    k_dinv<<<(N + 255) / 256, 256>>>(N);

    k_gemm1<<<(N + 15) / 16, 256>>>(x, W1, b1, N);

    long long th1 = (long long)E * (HID_C / 4);
    k_scatter<HID_C><<<(unsigned)((th1 + 255) / 256), 256>>>(src, dst, E);

    k_layer2<<<(N + 7) / 8, 256>>>(W2, b2, N);

    long long th2 = (long long)E * (OUT_C / 4);
    k_scatter<OUT_C><<<(unsigned)((th2 + 255) / 256), 256>>>(src, dst, E);

    long long thd = (long long)Ed * 8;
    k_decode<<<(unsigned)((thd + 255) / 256), 256>>>(de, Ed, out);
}

// round 2
// speedup vs baseline: 1.1589x; 1.1589x over previous
#include <cuda_runtime.h>

#define N_NODES_MAX 50000
#define IN_C  128
#define HID_C 64
#define OUT_C 32

// ---------------- scratch (no allocations allowed) ----------------
__device__ int   g_deg [N_NODES_MAX];
__device__ float g_dinv[N_NODES_MAX];
__device__ __align__(16) float g_xw1 [N_NODES_MAX * HID_C];  // x @ W1
__device__ __align__(16) float g_agg1[N_NODES_MAX * HID_C];  // layer1 aggregation
__device__ __align__(16) float g_hw2 [N_NODES_MAX * OUT_C];  // relu(h) @ W2
__device__ __align__(16) float g_agg2[N_NODES_MAX * OUT_C];  // layer2 aggregation = z

// ---------------- degree / norm ----------------
__global__ void k_deg_init(int n) {
    int i = blockIdx.x * blockDim.x + threadIdx.x;
    if (i < n) g_deg[i] = 1;  // self loop
}
__global__ void k_deg(const int* __restrict__ dst, int E) {
    int e = blockIdx.x * blockDim.x + threadIdx.x;
    if (e < E) atomicAdd(&g_deg[dst[e]], 1);
}
__global__ void k_dinv(int n) {
    int i = blockIdx.x * blockDim.x + threadIdx.x;
    if (i < n) g_dinv[i] = rsqrtf((float)g_deg[i]);
}

// ---------------- GEMM1: xw1 = x@W1 ; agg1 init = xw1*dinv^2 + b1 ----------------
// 64x64 output tile / block, 16x16 threads, 4x4 microtile per thread.
// x staged transposed in smem (broadcast reads); W staged as-is.
// Per k-step per thread: 2x LDS.128 -> 16 FMA (ratio 8:1, FMA-bound).
__global__ __launch_bounds__(256) void k_gemm1(const float* __restrict__ x,
                                               const float* __restrict__ W1,
                                               const float* __restrict__ b1, int n) {
    __shared__ __align__(16) float sXT[64 * 68];  // sXT[k*68 + r], 68*4=272=17*16 (f4-aligned rows)
    __shared__ __align__(16) float sW [64 * 64];  // sW[k*64 + c]

    const int tid = threadIdx.x;
    const int tx = tid & 15;          // output col group
    const int ty = tid >> 4;          // output row group
    const int row0 = blockIdx.x * 64;

    float acc[4][4];
#pragma unroll
    for (int i = 0; i < 4; i++)
#pragma unroll
        for (int j = 0; j < 4; j++) acc[i][j] = 0.f;

#pragma unroll
    for (int kt = 0; kt < 2; kt++) {
        // load x tile (64 rows x 64 k), transposed into sXT
        for (int i = tid; i < 64 * 64; i += 256) {
            int r = i >> 6, k = i & 63;
            int gr = row0 + r;
            float v = (gr < n) ? x[(size_t)gr * IN_C + kt * 64 + k] : 0.f;
            sXT[k * 68 + r] = v;
        }
        // load W tile (64 k x 64 c)
        for (int i = tid; i < 64 * 64; i += 256) {
            int k = i >> 6, c = i & 63;
            sW[i] = W1[(size_t)(kt * 64 + k) * HID_C + c];
        }
        __syncthreads();

#pragma unroll 16
        for (int k = 0; k < 64; k++) {
            float4 a4 = *(const float4*)(sXT + k * 68 + ty * 4);
            float4 b4 = *(const float4*)(sW + k * 64 + tx * 4);
            float av[4] = {a4.x, a4.y, a4.z, a4.w};
#pragma unroll
            for (int i = 0; i < 4; i++) {
                acc[i][0] = fmaf(av[i], b4.x, acc[i][0]);
                acc[i][1] = fmaf(av[i], b4.y, acc[i][1]);
                acc[i][2] = fmaf(av[i], b4.z, acc[i][2]);
                acc[i][3] = fmaf(av[i], b4.w, acc[i][3]);
            }
        }
        __syncthreads();
    }

    float4 bb = *(const float4*)(b1 + tx * 4);
#pragma unroll
    for (int i = 0; i < 4; i++) {
        int gr = row0 + ty * 4 + i;
        if (gr < n) {
            float di = g_dinv[gr], s = di * di;
            float4 v = make_float4(acc[i][0], acc[i][1], acc[i][2], acc[i][3]);
            *(float4*)(g_xw1 + (size_t)gr * HID_C + tx * 4) = v;
            float4 a = make_float4(fmaf(v.x, s, bb.x), fmaf(v.y, s, bb.y),
                                   fmaf(v.z, s, bb.z), fmaf(v.w, s, bb.w));
            *(float4*)(g_agg1 + (size_t)gr * HID_C + tx * 4) = a;
        }
    }
}

// ---------------- edge scatter: agg[d] += feat[s] * dinv[s]*dinv[d] ----------------
// C floats per row, C/4 threads per edge, vector red.global.add.v4.f32.
template <int C>
__global__ __launch_bounds__(256) void k_scatter(const int* __restrict__ src,
                                                 const int* __restrict__ dst, int E) {
    const int TPE = C / 4;
    const float* feat = (C == HID_C) ? g_xw1  : g_hw2;
    float*       agg  = (C == HID_C) ? g_agg1 : g_agg2;
    int g = blockIdx.x * blockDim.x + threadIdx.x;
    int e = g / TPE;
    int t = g % TPE;
    bool valid = (e < E);
    if (!valid) e = 0;
    int a = 0, d = 0; float norm = 0.f;
    if (t == 0) {
        a = src[e]; d = dst[e];
        norm = g_dinv[a] * g_dinv[d];
    }
    a    = __shfl_sync(0xffffffffu, a, 0, TPE);
    d    = __shfl_sync(0xffffffffu, d, 0, TPE);
    norm = __shfl_sync(0xffffffffu, norm, 0, TPE);
    float4 v = *(const float4*)(feat + (size_t)a * C + t * 4);
    v.x *= norm; v.y *= norm; v.z *= norm; v.w *= norm;
    if (valid) {
        float* p = agg + (size_t)d * C + t * 4;
        asm volatile("red.global.add.v4.f32 [%0], {%1,%2,%3,%4};"
                     :: "l"(p), "f"(v.x), "f"(v.y), "f"(v.z), "f"(v.w) : "memory");
    }
}

// ---------------- layer2: h = relu(agg1); hw2 = h@W2 ; agg2 init = hw2*dinv^2 + b2 ----------------
// 256 threads, 8 nodes per block (one warp each); lane = output col.
__global__ __launch_bounds__(256) void k_layer2(const float* __restrict__ W2,
                                                const float* __restrict__ b2, int n) {
    __shared__ float sWt[OUT_C * 68];  // sWt[c*68 + k], 68*4=272=17*16: aligned
    __shared__ float sh[8 * HID_C];
    int tid = threadIdx.x;
    for (int i = tid; i < HID_C * OUT_C; i += 256) {
        int k = i >> 5, c = i & 31;
        sWt[c * 68 + k] = W2[i];
    }
    __syncthreads();
    int warp = tid >> 5, lane = tid & 31;
    int node = blockIdx.x * 8 + warp;
    if (node >= n) return;
    float2 hv = *(const float2*)(g_agg1 + (size_t)node * HID_C + lane * 2);
    hv.x = fmaxf(hv.x, 0.f);
    hv.y = fmaxf(hv.y, 0.f);
    *(float2*)(sh + warp * HID_C + lane * 2) = hv;
    __syncwarp();
    float acc = 0.f;
    const float4* sh4 = (const float4*)(sh + warp * HID_C);
    const float4* w4  = (const float4*)(sWt + lane * 68);
#pragma unroll
    for (int kk = 0; kk < HID_C / 4; kk++) {
        float4 h4 = sh4[kk];
        float4 w  = w4[kk];
        acc = fmaf(h4.x, w.x, acc); acc = fmaf(h4.y, w.y, acc);
        acc = fmaf(h4.z, w.z, acc); acc = fmaf(h4.w, w.w, acc);
    }
    float di = g_dinv[node], s = di * di;
    g_hw2 [(size_t)node * OUT_C + lane] = acc;
    g_agg2[(size_t)node * OUT_C + lane] = fmaf(acc, s, b2[lane]);
}

// ---------------- decode: logits[e] = dot(z[a], z[b]) ----------------
// 8 lanes per edge, float4 gathers (full 128B line per row), segmented shuffle reduce.
__global__ __launch_bounds__(256) void k_decode(const int* __restrict__ de, int E,
                                                float* __restrict__ out) {
    int g = blockIdx.x * blockDim.x + threadIdx.x;
    int e = g >> 3, t = g & 7;
    bool valid = (e < E);
    if (!valid) e = 0;
    int a = 0, b = 0;
    if (t == 0) { a = de[e]; b = de[E + e]; }
    a = __shfl_sync(0xffffffffu, a, 0, 8);
    b = __shfl_sync(0xffffffffu, b, 0, 8);
    float4 za = *(const float4*)(g_agg2 + (size_t)a * OUT_C + t * 4);
    float4 zb = *(const float4*)(g_agg2 + (size_t)b * OUT_C + t * 4);
    float p = za.x * zb.x + za.y * zb.y + za.z * zb.z + za.w * zb.w;
    p += __shfl_down_sync(0xffffffffu, p, 4, 8);
    p += __shfl_down_sync(0xffffffffu, p, 2, 8);
    p += __shfl_down_sync(0xffffffffu, p, 1, 8);
    if (valid && t == 0) out[e] = p;
}

// ---------------- launch ----------------
extern "C" void kernel_launch(void* const* d_in, const int* in_sizes, int n_in,
                              void* d_out, int out_size) {
    const float* x  = (const float*)d_in[0];
    const float* W1 = (const float*)d_in[1];
    const float* b1 = (const float*)d_in[2];
    const float* W2 = (const float*)d_in[3];
    const float* b2 = (const float*)d_in[4];
    const int*   ei = (const int*)d_in[5];
    const int*   de = (const int*)d_in[6];

    int N  = in_sizes[0] / IN_C;
    int E  = in_sizes[5] / 2;
    int Ed = in_sizes[6] / 2;
    const int* src = ei;
    const int* dst = ei + E;
    float* out = (float*)d_out;

    k_deg_init<<<(N + 255) / 256, 256>>>(N);
    k_deg<<<(E + 255) / 256, 256>>>(dst, E);
    k_dinv<<<(N + 255) / 256, 256>>>(N);

    k_gemm1<<<(N + 63) / 64, 256>>>(x, W1, b1, N);

    long long th1 = (long long)E * (HID_C / 4);
    k_scatter<HID_C><<<(unsigned)((th1 + 255) / 256), 256>>>(src, dst, E);

    k_layer2<<<(N + 7) / 8, 256>>>(W2, b2, N);

    long long th2 = (long long)E * (OUT_C / 4);
    k_scatter<OUT_C><<<(unsigned)((th2 + 255) / 256), 256>>>(src, dst, E);

    long long thd = (long long)Ed * 8;
    k_decode<<<(unsigned)((thd + 255) / 256), 256>>>(de, Ed, out);
}

// round 7
// speedup vs baseline: 1.3303x; 1.1479x over previous
#include <cuda_runtime.h>

#define N_NODES_MAX 50000
#define IN_C  128
#define HID_C 64
#define OUT_C 32
#define NB_SCAN 196   // ceil(50000/256)

// ---------------- scratch (no allocations allowed) ----------------
__device__ int   g_deg [N_NODES_MAX];
__device__ int   g_rowstart[N_NODES_MAX];
__device__ int   g_cur [N_NODES_MAX];
__device__ int   g_bsum[256];
__device__ int   g_boff[256];
__device__ float g_dinv[N_NODES_MAX];
__device__ int   g_esrc[1600000];                              // CSR src lists (cap 2x E)
__device__ __align__(16) float g_xw1 [N_NODES_MAX * HID_C];    // x @ W1
__device__ __align__(16) float g_agg1[N_NODES_MAX * HID_C];    // layer1 aggregation
__device__ __align__(16) float g_hw2 [N_NODES_MAX * OUT_C];    // relu(h) @ W2
__device__ __align__(16) float g_agg2[N_NODES_MAX * OUT_C];    // layer2 aggregation = z

// ---------------- degree histogram ----------------
__global__ void k_deg_init(int n) {
    int i = blockIdx.x * blockDim.x + threadIdx.x;
    if (i < n) g_deg[i] = 1;  // self loop
}
__global__ void k_deg(const int* __restrict__ dst, int E) {
    int e = blockIdx.x * blockDim.x + threadIdx.x;
    if (e < E) atomicAdd(&g_deg[dst[e]], 1);
}

// ---------------- scan (3 phases) : rowstart = exclusive-prefix(deg-1) ----------------
__global__ __launch_bounds__(256) void k_scan1(int n) {
    __shared__ int ssum[8];
    int i = blockIdx.x * 256 + threadIdx.x;
    int v = (i < n) ? (g_deg[i] - 1) : 0;
#pragma unroll
    for (int o = 16; o > 0; o >>= 1) v += __shfl_down_sync(0xffffffffu, v, o);
    if ((threadIdx.x & 31) == 0) ssum[threadIdx.x >> 5] = v;
    __syncthreads();
    if (threadIdx.x < 8) {
        int s = ssum[threadIdx.x];
#pragma unroll
        for (int o = 4; o > 0; o >>= 1) s += __shfl_down_sync(0xffu, s, o);
        if (threadIdx.x == 0) g_bsum[blockIdx.x] = s;
    }
}
__global__ __launch_bounds__(256) void k_scan2() {
    __shared__ int sv[256];
    int t = threadIdx.x;
    int v = (t < NB_SCAN) ? g_bsum[t] : 0;
    sv[t] = v;
    __syncthreads();
#pragma unroll
    for (int o = 1; o < 256; o <<= 1) {
        int add = (t >= o) ? sv[t - o] : 0;
        __syncthreads();
        sv[t] += add;
        __syncthreads();
    }
    g_boff[t] = sv[t] - v;   // exclusive
}
__global__ __launch_bounds__(256) void k_scan3(int n) {
    __shared__ int swarp[8];
    int i = blockIdx.x * 256 + threadIdx.x;
    int lane = threadIdx.x & 31, warp = threadIdx.x >> 5;
    int deg = (i < n) ? g_deg[i] : 1;
    int v = deg - 1;
    int incl = v;
#pragma unroll
    for (int o = 1; o < 32; o <<= 1) {
        int t = __shfl_up_sync(0xffffffffu, incl, o);
        if (lane >= o) incl += t;
    }
    if (lane == 31) swarp[warp] = incl;
    __syncthreads();
    if (threadIdx.x < 8) {
        int s = swarp[threadIdx.x];
        int si = s;
#pragma unroll
        for (int o = 1; o < 8; o <<= 1) {
            int t = __shfl_up_sync(0xffu, si, o);
            if (threadIdx.x >= o) si += t;
        }
        swarp[threadIdx.x] = si - s;   // exclusive warp offsets
    }
    __syncthreads();
    if (i < n) {
        int rs = g_boff[blockIdx.x] + swarp[warp] + (incl - v);
        g_rowstart[i] = rs;
        g_cur[i] = rs;
        g_dinv[i] = rsqrtf((float)deg);
    }
}
__global__ void k_fill(const int* __restrict__ src, const int* __restrict__ dst, int E) {
    int e = blockIdx.x * blockDim.x + threadIdx.x;
    if (e < E) {
        int pos = atomicAdd(&g_cur[dst[e]], 1);
        g_esrc[pos] = src[e];
    }
}

// ---------------- GEMM1: xw1 = x@W1 ----------------
// 128x64 tile / block, 256 threads (16x16), 8x4 microtile, KT=32 k-tiles.
// smem: 32*132*4 + 32*64*4 = 25,088B (fits static limit; 2 CTA/SM possible).
// Per k-step: 3x LDS.128 -> 32 FMA.
__global__ __launch_bounds__(256) void k_gemm1(const float* __restrict__ x,
                                               const float* __restrict__ W1, int n) {
    __shared__ __align__(16) float sXT[32 * 132];  // sXT[k*132 + r], 132*4 = 33*16 (f4-aligned)
    __shared__ __align__(16) float sW [32 * 64];   // sW[k*64 + c]

    const int tid = threadIdx.x;
    const int tx = tid & 15;          // col group (4 cols)
    const int ty = tid >> 4;          // row group (8 rows)
    const int row0 = blockIdx.x * 128;

    float acc[8][4];
#pragma unroll
    for (int i = 0; i < 8; i++)
#pragma unroll
        for (int j = 0; j < 4; j++) acc[i][j] = 0.f;

#pragma unroll
    for (int kt = 0; kt < 4; kt++) {
        // x tile (128 rows x 32 k) transposed into sXT. Coalesced 128B global
        // reads per warp; staging store ~4-way bank conflict (small fraction).
        for (int i = tid; i < 128 * 32; i += 256) {
            int r = i >> 5, k = i & 31;
            int gr = row0 + r;
            float v = (gr < n) ? x[(size_t)gr * IN_C + kt * 32 + k] : 0.f;
            sXT[k * 132 + r] = v;
        }
        // W tile (32 k x 64 c)
        for (int i = tid; i < 32 * 64; i += 256) {
            int k = i >> 6, c = i & 63;
            sW[i] = W1[(size_t)(kt * 32 + k) * HID_C + c];
        }
        __syncthreads();

#pragma unroll 8
        for (int k = 0; k < 32; k++) {
            float4 a0 = *(const float4*)(sXT + k * 132 + ty * 8);
            float4 a1 = *(const float4*)(sXT + k * 132 + ty * 8 + 4);
            float4 b4 = *(const float4*)(sW + k * 64 + tx * 4);
            float av[8] = {a0.x, a0.y, a0.z, a0.w, a1.x, a1.y, a1.z, a1.w};
#pragma unroll
            for (int i = 0; i < 8; i++) {
                acc[i][0] = fmaf(av[i], b4.x, acc[i][0]);
                acc[i][1] = fmaf(av[i], b4.y, acc[i][1]);
                acc[i][2] = fmaf(av[i], b4.z, acc[i][2]);
                acc[i][3] = fmaf(av[i], b4.w, acc[i][3]);
            }
        }
        __syncthreads();
    }

#pragma unroll
    for (int i = 0; i < 8; i++) {
        int gr = row0 + ty * 8 + i;
        if (gr < n) {
            *(float4*)(g_xw1 + (size_t)gr * HID_C + tx * 4) =
                make_float4(acc[i][0], acc[i][1], acc[i][2], acc[i][3]);
        }
    }
}

// ---------------- gather aggregation: agg[d] = b + dinv[d]^2*feat[d] + sum dinv[s]dinv[d]*feat[s]
// C floats/row, C/4 lanes per node.
template <int C>
__global__ __launch_bounds__(256) void k_gather(const float* __restrict__ bias, int n) {
    const int LPN = C / 4;                      // lanes per node
    const float* feat = (C == HID_C) ? g_xw1  : g_hw2;
    float*       agg  = (C == HID_C) ? g_agg1 : g_agg2;
    int tid = threadIdx.x;
    int grp = tid / LPN, l = tid % LPN;
    int node = blockIdx.x * (256 / LPN) + grp;
    if (node >= n) return;

    float dn = g_dinv[node];
    int beg = g_rowstart[node];
    int end = beg + (g_deg[node] - 1);

    // self term + bias
    float4 acc = *(const float4*)(feat + (size_t)node * C + l * 4);
    float s = dn * dn;
    float4 bb = *(const float4*)(bias + l * 4);
    acc.x = fmaf(acc.x, s, bb.x); acc.y = fmaf(acc.y, s, bb.y);
    acc.z = fmaf(acc.z, s, bb.z); acc.w = fmaf(acc.w, s, bb.w);

    int j = beg;
    for (; j + 1 < end; j += 2) {
        int s0 = g_esrc[j], s1 = g_esrc[j + 1];
        float w0 = g_dinv[s0] * dn, w1 = g_dinv[s1] * dn;
        float4 v0 = *(const float4*)(feat + (size_t)s0 * C + l * 4);
        float4 v1 = *(const float4*)(feat + (size_t)s1 * C + l * 4);
        acc.x = fmaf(v0.x, w0, acc.x); acc.y = fmaf(v0.y, w0, acc.y);
        acc.z = fmaf(v0.z, w0, acc.z); acc.w = fmaf(v0.w, w0, acc.w);
        acc.x = fmaf(v1.x, w1, acc.x); acc.y = fmaf(v1.y, w1, acc.y);
        acc.z = fmaf(v1.z, w1, acc.z); acc.w = fmaf(v1.w, w1, acc.w);
    }
    if (j < end) {
        int s0 = g_esrc[j];
        float w0 = g_dinv[s0] * dn;
        float4 v0 = *(const float4*)(feat + (size_t)s0 * C + l * 4);
        acc.x = fmaf(v0.x, w0, acc.x); acc.y = fmaf(v0.y, w0, acc.y);
        acc.z = fmaf(v0.z, w0, acc.z); acc.w = fmaf(v0.w, w0, acc.w);
    }
    *(float4*)(agg + (size_t)node * C + l * 4) = acc;
}

// ---------------- layer2: hw2 = relu(agg1) @ W2 ----------------
__global__ __launch_bounds__(256) void k_layer2(const float* __restrict__ W2, int n) {
    __shared__ float sWt[OUT_C * 68];  // sWt[c*68 + k]
    __shared__ float sh[8 * HID_C];
    int tid = threadIdx.x;
    for (int i = tid; i < HID_C * OUT_C; i += 256) {
        int k = i >> 5, c = i & 31;
        sWt[c * 68 + k] = W2[i];
    }
    __syncthreads();
    int warp = tid >> 5, lane = tid & 31;
    int node = blockIdx.x * 8 + warp;
    if (node >= n) return;
    float2 hv = *(const float2*)(g_agg1 + (size_t)node * HID_C + lane * 2);
    hv.x = fmaxf(hv.x, 0.f);
    hv.y = fmaxf(hv.y, 0.f);
    *(float2*)(sh + warp * HID_C + lane * 2) = hv;
    __syncwarp();
    float acc = 0.f;
    const float4* sh4 = (const float4*)(sh + warp * HID_C);
    const float4* w4  = (const float4*)(sWt + lane * 68);
#pragma unroll
    for (int kk = 0; kk < HID_C / 4; kk++) {
        float4 h4 = sh4[kk];
        float4 w  = w4[kk];
        acc = fmaf(h4.x, w.x, acc); acc = fmaf(h4.y, w.y, acc);
        acc = fmaf(h4.z, w.z, acc); acc = fmaf(h4.w, w.w, acc);
    }
    g_hw2[(size_t)node * OUT_C + lane] = acc;
}

// ---------------- decode: logits[e] = dot(z[a], z[b]) ----------------
__global__ __launch_bounds__(256) void k_decode(const int* __restrict__ de, int E,
                                                float* __restrict__ out) {
    int g = blockIdx.x * blockDim.x + threadIdx.x;
    int e = g >> 3, t = g & 7;
    bool valid = (e < E);
    if (!valid) e = 0;
    int a = 0, b = 0;
    if (t == 0) { a = de[e]; b = de[E + e]; }
    a = __shfl_sync(0xffffffffu, a, 0, 8);
    b = __shfl_sync(0xffffffffu, b, 0, 8);
    float4 za = *(const float4*)(g_agg2 + (size_t)a * OUT_C + t * 4);
    float4 zb = *(const float4*)(g_agg2 + (size_t)b * OUT_C + t * 4);
    float p = za.x * zb.x + za.y * zb.y + za.z * zb.z + za.w * zb.w;
    p += __shfl_down_sync(0xffffffffu, p, 4, 8);
    p += __shfl_down_sync(0xffffffffu, p, 2, 8);
    p += __shfl_down_sync(0xffffffffu, p, 1, 8);
    if (valid && t == 0) out[e] = p;
}

// ---------------- launch ----------------
extern "C" void kernel_launch(void* const* d_in, const int* in_sizes, int n_in,
                              void* d_out, int out_size) {
    const float* x  = (const float*)d_in[0];
    const float* W1 = (const float*)d_in[1];
    const float* b1 = (const float*)d_in[2];
    const float* W2 = (const float*)d_in[3];
    const float* b2 = (const float*)d_in[4];
    const int*   ei = (const int*)d_in[5];
    const int*   de = (const int*)d_in[6];

    int N  = in_sizes[0] / IN_C;
    int E  = in_sizes[5] / 2;
    int Ed = in_sizes[6] / 2;
    const int* src = ei;
    const int* dst = ei + E;
    float* out = (float*)d_out;

    int nb = (N + 255) / 256;

    k_deg_init<<<nb, 256>>>(N);
    k_deg<<<(E + 255) / 256, 256>>>(dst, E);
    k_scan1<<<nb, 256>>>(N);
    k_scan2<<<1, 256>>>();
    k_scan3<<<nb, 256>>>(N);
    k_fill<<<(E + 255) / 256, 256>>>(src, dst, E);

    k_gemm1<<<(N + 127) / 128, 256>>>(x, W1, N);

    k_gather<HID_C><<<(N * (HID_C / 4) + 255) / 256, 256>>>(b1, N);
    k_layer2<<<(N + 7) / 8, 256>>>(W2, N);
    k_gather<OUT_C><<<(N * (OUT_C / 4) + 255) / 256, 256>>>(b2, N);

    long long thd = (long long)Ed * 8;
    k_decode<<<(unsigned)((thd + 255) / 256), 256>>>(de, Ed, out);
}

// round 8
// speedup vs baseline: 1.7276x; 1.2987x over previous
#include <cuda_runtime.h>
#include <cuda_fp16.h>

#define N_NODES_MAX 50000
#define IN_C  128
#define HID_C 64
#define OUT_C 32

// ---------------- scratch (no allocations allowed) ----------------
__device__ int   g_deg [N_NODES_MAX];
__device__ int   g_rowstart[N_NODES_MAX];
__device__ int   g_cur [N_NODES_MAX];
__device__ int   g_bsum[256];
__device__ float g_dinv[N_NODES_MAX];
__device__ int   g_esrc[1600000];                              // CSR src lists (cap 2x E)
__device__ __align__(16) float  g_xw1[N_NODES_MAX * HID_C];    // x @ W1
__device__ __align__(16) float  g_hw2[N_NODES_MAX * OUT_C];    // relu(h) @ W2
__device__ __align__(16) __half g_z16[N_NODES_MAX * OUT_C];    // z (fp16, decode only)

// ---------------- degree histogram ----------------
__global__ void k_deg_init(int n) {
    int i = blockIdx.x * blockDim.x + threadIdx.x;
    if (i < n) g_deg[i] = 1;  // self loop
}
__global__ void k_deg(const int* __restrict__ dst, int E) {
    int e = blockIdx.x * blockDim.x + threadIdx.x;
    if (e < E) atomicAdd(&g_deg[dst[e]], 1);
}

// ---------------- scan phase 1: per-block sums of (deg-1) ----------------
__global__ __launch_bounds__(256) void k_scan1(int n) {
    __shared__ int ssum[8];
    int i = blockIdx.x * 256 + threadIdx.x;
    int v = (i < n) ? (g_deg[i] - 1) : 0;
#pragma unroll
    for (int o = 16; o > 0; o >>= 1) v += __shfl_down_sync(0xffffffffu, v, o);
    if ((threadIdx.x & 31) == 0) ssum[threadIdx.x >> 5] = v;
    __syncthreads();
    if (threadIdx.x < 8) {
        int s = ssum[threadIdx.x];
#pragma unroll
        for (int o = 4; o > 0; o >>= 1) s += __shfl_down_sync(0xffu, s, o);
        if (threadIdx.x == 0) g_bsum[blockIdx.x] = s;
    }
}

// ---------------- scan phase 2 (merged): block offset computed in-block ----------------
__global__ __launch_bounds__(256) void k_scan3(int n) {
    __shared__ int swarp[8];
    __shared__ int s_off;
    int bid = blockIdx.x;
    // warp 0: offset = sum of g_bsum[j < bid]
    if (threadIdx.x < 32) {
        int s = 0;
        for (int j = threadIdx.x; j < bid; j += 32) s += g_bsum[j];
#pragma unroll
        for (int o = 16; o > 0; o >>= 1) s += __shfl_down_sync(0xffffffffu, s, o);
        if (threadIdx.x == 0) s_off = s;
    }
    int i = bid * 256 + threadIdx.x;
    int lane = threadIdx.x & 31, warp = threadIdx.x >> 5;
    int deg = (i < n) ? g_deg[i] : 1;
    int v = deg - 1;
    int incl = v;
#pragma unroll
    for (int o = 1; o < 32; o <<= 1) {
        int t = __shfl_up_sync(0xffffffffu, incl, o);
        if (lane >= o) incl += t;
    }
    if (lane == 31) swarp[warp] = incl;
    __syncthreads();
    if (threadIdx.x < 8) {
        int s = swarp[threadIdx.x];
        int si = s;
#pragma unroll
        for (int o = 1; o < 8; o <<= 1) {
            int t = __shfl_up_sync(0xffu, si, o);
            if (threadIdx.x >= o) si += t;
        }
        swarp[threadIdx.x] = si - s;   // exclusive warp offsets
    }
    __syncthreads();
    if (i < n) {
        int rs = s_off + swarp[warp] + (incl - v);
        g_rowstart[i] = rs;
        g_cur[i] = rs;
        g_dinv[i] = rsqrtf((float)deg);
    }
}
__global__ void k_fill(const int* __restrict__ src, const int* __restrict__ dst, int E) {
    int e = blockIdx.x * blockDim.x + threadIdx.x;
    if (e < E) {
        int pos = atomicAdd(&g_cur[dst[e]], 1);
        g_esrc[pos] = src[e];
    }
}

// ---------------- GEMM1: xw1 = x@W1 ----------------
// 128x64 tile / block, 256 threads (16x16), 8x4 microtile, KT=32 k-tiles.
__global__ __launch_bounds__(256) void k_gemm1(const float* __restrict__ x,
                                               const float* __restrict__ W1, int n) {
    __shared__ __align__(16) float sXT[32 * 132];  // sXT[k*132 + r]
    __shared__ __align__(16) float sW [32 * 64];   // sW[k*64 + c]

    const int tid = threadIdx.x;
    const int tx = tid & 15;
    const int ty = tid >> 4;
    const int row0 = blockIdx.x * 128;

    float acc[8][4];
#pragma unroll
    for (int i = 0; i < 8; i++)
#pragma unroll
        for (int j = 0; j < 4; j++) acc[i][j] = 0.f;

#pragma unroll
    for (int kt = 0; kt < 4; kt++) {
        for (int i = tid; i < 128 * 32; i += 256) {
            int r = i >> 5, k = i & 31;
            int gr = row0 + r;
            float v = (gr < n) ? x[(size_t)gr * IN_C + kt * 32 + k] : 0.f;
            sXT[k * 132 + r] = v;
        }
        for (int i = tid; i < 32 * 64; i += 256) {
            int k = i >> 6, c = i & 63;
            sW[i] = W1[(size_t)(kt * 32 + k) * HID_C + c];
        }
        __syncthreads();

#pragma unroll 8
        for (int k = 0; k < 32; k++) {
            float4 a0 = *(const float4*)(sXT + k * 132 + ty * 8);
            float4 a1 = *(const float4*)(sXT + k * 132 + ty * 8 + 4);
            float4 b4 = *(const float4*)(sW + k * 64 + tx * 4);
            float av[8] = {a0.x, a0.y, a0.z, a0.w, a1.x, a1.y, a1.z, a1.w};
#pragma unroll
            for (int i = 0; i < 8; i++) {
                acc[i][0] = fmaf(av[i], b4.x, acc[i][0]);
                acc[i][1] = fmaf(av[i], b4.y, acc[i][1]);
                acc[i][2] = fmaf(av[i], b4.z, acc[i][2]);
                acc[i][3] = fmaf(av[i], b4.w, acc[i][3]);
            }
        }
        __syncthreads();
    }

#pragma unroll
    for (int i = 0; i < 8; i++) {
        int gr = row0 + ty * 8 + i;
        if (gr < n) {
            *(float4*)(g_xw1 + (size_t)gr * HID_C + tx * 4) =
                make_float4(acc[i][0], acc[i][1], acc[i][2], acc[i][3]);
        }
    }
}

// ---------------- fused: gather layer1 (+b1, relu) then @W2 -> g_hw2 ----------------
// 16 nodes per 256-thread block. Phase A: 16 lanes/node gather 64-dim agg into smem.
// Phase B: each thread computes 2 of the 32 outputs for one node.
__global__ __launch_bounds__(256) void k_gather1_layer2(const float* __restrict__ b1,
                                                        const float* __restrict__ W2, int n) {
    __shared__ __align__(16) float sh[16 * 68];   // relu(agg1) rows, padded
    __shared__ float sW2[HID_C * OUT_C];          // sW2[k*32 + c]
    int tid = threadIdx.x;
    for (int i = tid; i < HID_C * OUT_C; i += 256) sW2[i] = W2[i];

    int grp = tid >> 4, l = tid & 15;             // node group, lane (4 dims)
    int node = blockIdx.x * 16 + grp;
    if (node < n) {
        float dn = g_dinv[node];
        int beg = g_rowstart[node];
        int end = beg + (g_deg[node] - 1);

        float4 acc = *(const float4*)(g_xw1 + (size_t)node * HID_C + l * 4);
        float s = dn * dn;
        float4 bb = *(const float4*)(b1 + l * 4);
        acc.x = fmaf(acc.x, s, bb.x); acc.y = fmaf(acc.y, s, bb.y);
        acc.z = fmaf(acc.z, s, bb.z); acc.w = fmaf(acc.w, s, bb.w);

        int j = beg;
        for (; j + 1 < end; j += 2) {
            int s0 = g_esrc[j], s1 = g_esrc[j + 1];
            float w0 = g_dinv[s0] * dn, w1 = g_dinv[s1] * dn;
            float4 v0 = *(const float4*)(g_xw1 + (size_t)s0 * HID_C + l * 4);
            float4 v1 = *(const float4*)(g_xw1 + (size_t)s1 * HID_C + l * 4);
            acc.x = fmaf(v0.x, w0, acc.x); acc.y = fmaf(v0.y, w0, acc.y);
            acc.z = fmaf(v0.z, w0, acc.z); acc.w = fmaf(v0.w, w0, acc.w);
            acc.x = fmaf(v1.x, w1, acc.x); acc.y = fmaf(v1.y, w1, acc.y);
            acc.z = fmaf(v1.z, w1, acc.z); acc.w = fmaf(v1.w, w1, acc.w);
        }
        if (j < end) {
            int s0 = g_esrc[j];
            float w0 = g_dinv[s0] * dn;
            float4 v0 = *(const float4*)(g_xw1 + (size_t)s0 * HID_C + l * 4);
            acc.x = fmaf(v0.x, w0, acc.x); acc.y = fmaf(v0.y, w0, acc.y);
            acc.z = fmaf(v0.z, w0, acc.z); acc.w = fmaf(v0.w, w0, acc.w);
        }
        // relu -> smem
        float* dsth = sh + grp * 68 + l * 4;
        dsth[0] = fmaxf(acc.x, 0.f);
        dsth[1] = fmaxf(acc.y, 0.f);
        dsth[2] = fmaxf(acc.z, 0.f);
        dsth[3] = fmaxf(acc.w, 0.f);
    }
    __syncthreads();

    // Phase B: nd = tid>>4, c = tid&15 ; outputs c and c+16
    int nd = tid >> 4, c = tid & 15;
    int gnode = blockIdx.x * 16 + nd;
    if (gnode >= n) return;
    const float* hrow = sh + nd * 68;
    float a0 = 0.f, a1 = 0.f;
#pragma unroll 8
    for (int k = 0; k < HID_C; k++) {
        float hk = hrow[k];
        a0 = fmaf(hk, sW2[k * OUT_C + c], a0);
        a1 = fmaf(hk, sW2[k * OUT_C + c + 16], a1);
    }
    g_hw2[(size_t)gnode * OUT_C + c]      = a0;
    g_hw2[(size_t)gnode * OUT_C + c + 16] = a1;
}

// ---------------- gather layer2 (+b2) -> z (fp16) ----------------
// 8 lanes per node (float4 each), 32 nodes per block.
__global__ __launch_bounds__(256) void k_gather2(const float* __restrict__ b2, int n) {
    int tid = threadIdx.x;
    int grp = tid >> 3, l = tid & 7;
    int node = blockIdx.x * 32 + grp;
    if (node >= n) return;

    float dn = g_dinv[node];
    int beg = g_rowstart[node];
    int end = beg + (g_deg[node] - 1);

    float4 acc = *(const float4*)(g_hw2 + (size_t)node * OUT_C + l * 4);
    float s = dn * dn;
    float4 bb = *(const float4*)(b2 + l * 4);
    acc.x = fmaf(acc.x, s, bb.x); acc.y = fmaf(acc.y, s, bb.y);
    acc.z = fmaf(acc.z, s, bb.z); acc.w = fmaf(acc.w, s, bb.w);

    int j = beg;
    for (; j + 1 < end; j += 2) {
        int s0 = g_esrc[j], s1 = g_esrc[j + 1];
        float w0 = g_dinv[s0] * dn, w1 = g_dinv[s1] * dn;
        float4 v0 = *(const float4*)(g_hw2 + (size_t)s0 * OUT_C + l * 4);
        float4 v1 = *(const float4*)(g_hw2 + (size_t)s1 * OUT_C + l * 4);
        acc.x = fmaf(v0.x, w0, acc.x); acc.y = fmaf(v0.y, w0, acc.y);
        acc.z = fmaf(v0.z, w0, acc.z); acc.w = fmaf(v0.w, w0, acc.w);
        acc.x = fmaf(v1.x, w1, acc.x); acc.y = fmaf(v1.y, w1, acc.y);
        acc.z = fmaf(v1.z, w1, acc.z); acc.w = fmaf(v1.w, w1, acc.w);
    }
    if (j < end) {
        int s0 = g_esrc[j];
        float w0 = g_dinv[s0] * dn;
        float4 v0 = *(const float4*)(g_hw2 + (size_t)s0 * OUT_C + l * 4);
        acc.x = fmaf(v0.x, w0, acc.x); acc.y = fmaf(v0.y, w0, acc.y);
        acc.z = fmaf(v0.z, w0, acc.z); acc.w = fmaf(v0.w, w0, acc.w);
    }
    __half2 p0 = __floats2half2_rn(acc.x, acc.y);
    __half2 p1 = __floats2half2_rn(acc.z, acc.w);
    uint2 u;
    u.x = *(const unsigned int*)&p0;
    u.y = *(const unsigned int*)&p1;
    *(uint2*)(g_z16 + (size_t)node * OUT_C + l * 4) = u;
}

// ---------------- decode: logits[e] = dot(z[a], z[b]) (fp16 z, fp32 math) ----------------
// 4 lanes per edge; each lane loads 16B (8 halves) of each z row (64B rows).
__global__ __launch_bounds__(256) void k_decode(const int* __restrict__ de, int E,
                                                float* __restrict__ out) {
    int g = blockIdx.x * blockDim.x + threadIdx.x;
    int e = g >> 2, t = g & 3;
    bool valid = (e < E);
    if (!valid) e = 0;
    int a = 0, b = 0;
    if (t == 0) { a = de[e]; b = de[E + e]; }
    a = __shfl_sync(0xffffffffu, a, 0, 4);
    b = __shfl_sync(0xffffffffu, b, 0, 4);
    uint4 ua = *(const uint4*)(g_z16 + (size_t)a * OUT_C + t * 8);
    uint4 ub = *(const uint4*)(g_z16 + (size_t)b * OUT_C + t * 8);
    float p = 0.f;
    const unsigned int* pa = &ua.x;
    const unsigned int* pb = &ub.x;
#pragma unroll
    for (int i = 0; i < 4; i++) {
        float2 fa = __half22float2(*(const __half2*)&pa[i]);
        float2 fb = __half22float2(*(const __half2*)&pb[i]);
        p = fmaf(fa.x, fb.x, p);
        p = fmaf(fa.y, fb.y, p);
    }
    p += __shfl_down_sync(0xffffffffu, p, 2, 4);
    p += __shfl_down_sync(0xffffffffu, p, 1, 4);
    if (valid && t == 0) out[e] = p;
}

// ---------------- launch ----------------
extern "C" void kernel_launch(void* const* d_in, const int* in_sizes, int n_in,
                              void* d_out, int out_size) {
    const float* x  = (const float*)d_in[0];
    const float* W1 = (const float*)d_in[1];
    const float* b1 = (const float*)d_in[2];
    const float* W2 = (const float*)d_in[3];
    const float* b2 = (const float*)d_in[4];
    const int*   ei = (const int*)d_in[5];
    const int*   de = (const int*)d_in[6];

    int N  = in_sizes[0] / IN_C;
    int E  = in_sizes[5] / 2;
    int Ed = in_sizes[6] / 2;
    const int* src = ei;
    const int* dst = ei + E;
    float* out = (float*)d_out;

    int nb = (N + 255) / 256;

    k_deg_init<<<nb, 256>>>(N);
    k_deg<<<(E + 255) / 256, 256>>>(dst, E);
    k_scan1<<<nb, 256>>>(N);
    k_scan3<<<nb, 256>>>(N);
    k_fill<<<(E + 255) / 256, 256>>>(src, dst, E);

    k_gemm1<<<(N + 127) / 128, 256>>>(x, W1, N);

    k_gather1_layer2<<<(N + 15) / 16, 256>>>(b1, W2, N);
    k_gather2<<<(N + 31) / 32, 256>>>(b2, N);

    long long thd = (long long)Ed * 4;
    k_decode<<<(unsigned)((thd + 255) / 256), 256>>>(de, Ed, out);
}

// round 9
// speedup vs baseline: 1.7819x; 1.0314x over previous
#include <cuda_runtime.h>
#include <cuda_fp16.h>

#define N_NODES_MAX 50000
#define IN_C  128
#define HID_C 64
#define OUT_C 32

// ---------------- scratch (no allocations allowed) ----------------
// g_deg counts IN-EDGES only (self loop handled as +1 at use sites).
// It is zero-initialized at module load and re-zeroed by k_decode at the end
// of every launch, so every execution starts from deg==0.
__device__ int   g_deg [N_NODES_MAX];
__device__ int   g_rowstart[N_NODES_MAX];
__device__ int   g_cur [N_NODES_MAX];
__device__ float g_dinv[N_NODES_MAX];
__device__ int   g_esrc[1600000];                              // CSR src lists (cap 2x E)
__device__ __align__(16) __half g_xw1h[N_NODES_MAX * HID_C];   // x @ W1 (fp16 storage)
__device__ __align__(16) float  g_hw2 [N_NODES_MAX * OUT_C];   // relu(h) @ W2
__device__ __align__(16) __half g_z16 [N_NODES_MAX * OUT_C];   // z (fp16, decode only)

// ---------------- degree histogram (in-edges) ----------------
__global__ void k_deg(const int* __restrict__ dst, int E) {
    int e = blockIdx.x * blockDim.x + threadIdx.x;
    if (e < E) atomicAdd(&g_deg[dst[e]], 1);
}

// ---------------- single-kernel scan: rowstart = exclusive-prefix(deg) ----------------
// Each block computes its own offset by summing deg[0 .. bid*256) directly
// (<=50k coalesced int loads spread over 256 threads), then intra-block scan.
__global__ __launch_bounds__(256) void k_scan(int n) {
    __shared__ int swarp[8];
    __shared__ int soff[8];
    int bid = blockIdx.x;
    int tid = threadIdx.x;
    int lane = tid & 31, warp = tid >> 5;

    // block offset = sum deg[0 .. bid*256)
    int limit = bid * 256;
    int s = 0;
    for (int j = tid; j < limit; j += 256) s += g_deg[j];
#pragma unroll
    for (int o = 16; o > 0; o >>= 1) s += __shfl_down_sync(0xffffffffu, s, o);
    if (lane == 0) soff[warp] = s;
    __syncthreads();
    if (tid < 8) {
        int t = soff[tid];
#pragma unroll
        for (int o = 4; o > 0; o >>= 1) t += __shfl_down_sync(0xffu, t, o);
        if (tid == 0) soff[0] = t;
    }
    __syncthreads();
    int off = soff[0];

    // intra-block exclusive scan of deg
    int i = bid * 256 + tid;
    int deg = (i < n) ? g_deg[i] : 0;
    int incl = deg;
#pragma unroll
    for (int o = 1; o < 32; o <<= 1) {
        int t = __shfl_up_sync(0xffffffffu, incl, o);
        if (lane >= o) incl += t;
    }
    if (lane == 31) swarp[warp] = incl;
    __syncthreads();
    if (tid < 8) {
        int t = swarp[tid];
        int si = t;
#pragma unroll
        for (int o = 1; o < 8; o <<= 1) {
            int u = __shfl_up_sync(0xffu, si, o);
            if (tid >= o) si += u;
        }
        swarp[tid] = si - t;   // exclusive warp offsets
    }
    __syncthreads();
    if (i < n) {
        int rs = off + swarp[warp] + (incl - deg);
        g_rowstart[i] = rs;
        g_cur[i] = rs;
        g_dinv[i] = rsqrtf((float)(deg + 1));
    }
}
__global__ void k_fill(const int* __restrict__ src, const int* __restrict__ dst, int E) {
    int e = blockIdx.x * blockDim.x + threadIdx.x;
    if (e < E) {
        int pos = atomicAdd(&g_cur[dst[e]], 1);
        g_esrc[pos] = src[e];
    }
}

// ---------------- GEMM1: xw1 = x@W1 (fp32 math, fp16 store) ----------------
// 128x64 tile / block, 256 threads (16x16), 8x4 microtile, KT=32 k-tiles.
__global__ __launch_bounds__(256) void k_gemm1(const float* __restrict__ x,
                                               const float* __restrict__ W1, int n) {
    __shared__ __align__(16) float sXT[32 * 132];  // sXT[k*132 + r]
    __shared__ __align__(16) float sW [32 * 64];   // sW[k*64 + c]

    const int tid = threadIdx.x;
    const int tx = tid & 15;
    const int ty = tid >> 4;
    const int row0 = blockIdx.x * 128;

    float acc[8][4];
#pragma unroll
    for (int i = 0; i < 8; i++)
#pragma unroll
        for (int j = 0; j < 4; j++) acc[i][j] = 0.f;

#pragma unroll
    for (int kt = 0; kt < 4; kt++) {
        for (int i = tid; i < 128 * 32; i += 256) {
            int r = i >> 5, k = i & 31;
            int gr = row0 + r;
            float v = (gr < n) ? x[(size_t)gr * IN_C + kt * 32 + k] : 0.f;
            sXT[k * 132 + r] = v;
        }
        for (int i = tid; i < 32 * 64; i += 256) {
            int k = i >> 6, c = i & 63;
            sW[i] = W1[(size_t)(kt * 32 + k) * HID_C + c];
        }
        __syncthreads();

#pragma unroll 8
        for (int k = 0; k < 32; k++) {
            float4 a0 = *(const float4*)(sXT + k * 132 + ty * 8);
            float4 a1 = *(const float4*)(sXT + k * 132 + ty * 8 + 4);
            float4 b4 = *(const float4*)(sW + k * 64 + tx * 4);
            float av[8] = {a0.x, a0.y, a0.z, a0.w, a1.x, a1.y, a1.z, a1.w};
#pragma unroll
            for (int i = 0; i < 8; i++) {
                acc[i][0] = fmaf(av[i], b4.x, acc[i][0]);
                acc[i][1] = fmaf(av[i], b4.y, acc[i][1]);
                acc[i][2] = fmaf(av[i], b4.z, acc[i][2]);
                acc[i][3] = fmaf(av[i], b4.w, acc[i][3]);
            }
        }
        __syncthreads();
    }

#pragma unroll
    for (int i = 0; i < 8; i++) {
        int gr = row0 + ty * 8 + i;
        if (gr < n) {
            __half2 p0 = __floats2half2_rn(acc[i][0], acc[i][1]);
            __half2 p1 = __floats2half2_rn(acc[i][2], acc[i][3]);
            uint2 u;
            u.x = *(const unsigned int*)&p0;
            u.y = *(const unsigned int*)&p1;
            *(uint2*)(g_xw1h + (size_t)gr * HID_C + tx * 4) = u;
        }
    }
}

// ---------------- fused: gather layer1 (+b1, relu) then @W2 -> g_hw2 ----------------
// 16 nodes per 256-thread block. Phase A: 16 lanes/node gather 64-dim agg (fp16 rows)
// into smem with fp32 accumulation. Phase B: each thread computes 2 of 32 outputs.
__global__ __launch_bounds__(256) void k_gather1_layer2(const float* __restrict__ b1,
                                                        const float* __restrict__ W2, int n) {
    __shared__ __align__(16) float sh[16 * 68];   // relu(agg1) rows, padded
    __shared__ float sW2[HID_C * OUT_C];          // sW2[k*32 + c]
    int tid = threadIdx.x;
    for (int i = tid; i < HID_C * OUT_C; i += 256) sW2[i] = W2[i];

    int grp = tid >> 4, l = tid & 15;             // node group, lane (4 dims = 8B fp16)
    int node = blockIdx.x * 16 + grp;
    if (node < n) {
        float dn = g_dinv[node];
        int beg = g_rowstart[node];
        int end = beg + g_deg[node];

        // self term + bias
        uint2 us = *(const uint2*)(g_xw1h + (size_t)node * HID_C + l * 4);
        float2 s0 = __half22float2(*(const __half2*)&us.x);
        float2 s1 = __half22float2(*(const __half2*)&us.y);
        float s = dn * dn;
        float4 bb = *(const float4*)(b1 + l * 4);
        float4 acc;
        acc.x = fmaf(s0.x, s, bb.x); acc.y = fmaf(s0.y, s, bb.y);
        acc.z = fmaf(s1.x, s, bb.z); acc.w = fmaf(s1.y, s, bb.w);

        int j = beg;
        for (; j + 1 < end; j += 2) {
            int n0 = g_esrc[j], n1 = g_esrc[j + 1];
            float w0 = g_dinv[n0] * dn, w1 = g_dinv[n1] * dn;
            uint2 u0 = *(const uint2*)(g_xw1h + (size_t)n0 * HID_C + l * 4);
            uint2 u1 = *(const uint2*)(g_xw1h + (size_t)n1 * HID_C + l * 4);
            float2 a0 = __half22float2(*(const __half2*)&u0.x);
            float2 a1 = __half22float2(*(const __half2*)&u0.y);
            float2 c0 = __half22float2(*(const __half2*)&u1.x);
            float2 c1 = __half22float2(*(const __half2*)&u1.y);
            acc.x = fmaf(a0.x, w0, acc.x); acc.y = fmaf(a0.y, w0, acc.y);
            acc.z = fmaf(a1.x, w0, acc.z); acc.w = fmaf(a1.y, w0, acc.w);
            acc.x = fmaf(c0.x, w1, acc.x); acc.y = fmaf(c0.y, w1, acc.y);
            acc.z = fmaf(c1.x, w1, acc.z); acc.w = fmaf(c1.y, w1, acc.w);
        }
        if (j < end) {
            int n0 = g_esrc[j];
            float w0 = g_dinv[n0] * dn;
            uint2 u0 = *(const uint2*)(g_xw1h + (size_t)n0 * HID_C + l * 4);
            float2 a0 = __half22float2(*(const __half2*)&u0.x);
            float2 a1 = __half22float2(*(const __half2*)&u0.y);
            acc.x = fmaf(a0.x, w0, acc.x); acc.y = fmaf(a0.y, w0, acc.y);
            acc.z = fmaf(a1.x, w0, acc.z); acc.w = fmaf(a1.y, w0, acc.w);
        }
        // relu -> smem
        float* dsth = sh + grp * 68 + l * 4;
        dsth[0] = fmaxf(acc.x, 0.f);
        dsth[1] = fmaxf(acc.y, 0.f);
        dsth[2] = fmaxf(acc.z, 0.f);
        dsth[3] = fmaxf(acc.w, 0.f);
    }
    __syncthreads();

    // Phase B: nd = tid>>4, c = tid&15 ; outputs c and c+16
    int nd = tid >> 4, c = tid & 15;
    int gnode = blockIdx.x * 16 + nd;
    if (gnode >= n) return;
    const float* hrow = sh + nd * 68;
    float a0 = 0.f, a1 = 0.f;
#pragma unroll 8
    for (int k = 0; k < HID_C; k++) {
        float hk = hrow[k];
        a0 = fmaf(hk, sW2[k * OUT_C + c], a0);
        a1 = fmaf(hk, sW2[k * OUT_C + c + 16], a1);
    }
    g_hw2[(size_t)gnode * OUT_C + c]      = a0;
    g_hw2[(size_t)gnode * OUT_C + c + 16] = a1;
}

// ---------------- gather layer2 (+b2) -> z (fp16) ----------------
// 8 lanes per node (float4 each), 32 nodes per block.
__global__ __launch_bounds__(256) void k_gather2(const float* __restrict__ b2, int n) {
    int tid = threadIdx.x;
    int grp = tid >> 3, l = tid & 7;
    int node = blockIdx.x * 32 + grp;
    if (node >= n) return;

    float dn = g_dinv[node];
    int beg = g_rowstart[node];
    int end = beg + g_deg[node];

    float4 acc = *(const float4*)(g_hw2 + (size_t)node * OUT_C + l * 4);
    float s = dn * dn;
    float4 bb = *(const float4*)(b2 + l * 4);
    acc.x = fmaf(acc.x, s, bb.x); acc.y = fmaf(acc.y, s, bb.y);
    acc.z = fmaf(acc.z, s, bb.z); acc.w = fmaf(acc.w, s, bb.w);

    int j = beg;
    for (; j + 1 < end; j += 2) {
        int s0 = g_esrc[j], s1 = g_esrc[j + 1];
        float w0 = g_dinv[s0] * dn, w1 = g_dinv[s1] * dn;
        float4 v0 = *(const float4*)(g_hw2 + (size_t)s0 * OUT_C + l * 4);
        float4 v1 = *(const float4*)(g_hw2 + (size_t)s1 * OUT_C + l * 4);
        acc.x = fmaf(v0.x, w0, acc.x); acc.y = fmaf(v0.y, w0, acc.y);
        acc.z = fmaf(v0.z, w0, acc.z); acc.w = fmaf(v0.w, w0, acc.w);
        acc.x = fmaf(v1.x, w1, acc.x); acc.y = fmaf(v1.y, w1, acc.y);
        acc.z = fmaf(v1.z, w1, acc.z); acc.w = fmaf(v1.w, w1, acc.w);
    }
    if (j < end) {
        int s0 = g_esrc[j];
        float w0 = g_dinv[s0] * dn;
        float4 v0 = *(const float4*)(g_hw2 + (size_t)s0 * OUT_C + l * 4);
        acc.x = fmaf(v0.x, w0, acc.x); acc.y = fmaf(v0.y, w0, acc.y);
        acc.z = fmaf(v0.z, w0, acc.z); acc.w = fmaf(v0.w, w0, acc.w);
    }
    __half2 p0 = __floats2half2_rn(acc.x, acc.y);
    __half2 p1 = __floats2half2_rn(acc.z, acc.w);
    uint2 u;
    u.x = *(const unsigned int*)&p0;
    u.y = *(const unsigned int*)&p1;
    *(uint2*)(g_z16 + (size_t)node * OUT_C + l * 4) = u;
}

// ---------------- decode: logits[e] = dot(z[a], z[b]) (fp16 z, fp32 math) ----------------
// 4 lanes per edge; each lane loads 16B (8 halves) of each z row (64B rows).
// Also resets g_deg to 0 for the next launch (keeps per-call state invariant).
__global__ __launch_bounds__(256) void k_decode(const int* __restrict__ de, int E,
                                                float* __restrict__ out, int n) {
    int g = blockIdx.x * blockDim.x + threadIdx.x;
    if (g < n) g_deg[g] = 0;   // restore deg==0 invariant for next call
    int e = g >> 2, t = g & 3;
    bool valid = (e < E);
    if (!valid) e = 0;
    int a = 0, b = 0;
    if (t == 0) { a = de[e]; b = de[E + e]; }
    a = __shfl_sync(0xffffffffu, a, 0, 4);
    b = __shfl_sync(0xffffffffu, b, 0, 4);
    uint4 ua = *(const uint4*)(g_z16 + (size_t)a * OUT_C + t * 8);
    uint4 ub = *(const uint4*)(g_z16 + (size_t)b * OUT_C + t * 8);
    float p = 0.f;
    const unsigned int* pa = &ua.x;
    const unsigned int* pb = &ub.x;
#pragma unroll
    for (int i = 0; i < 4; i++) {
        float2 fa = __half22float2(*(const __half2*)&pa[i]);
        float2 fb = __half22float2(*(const __half2*)&pb[i]);
        p = fmaf(fa.x, fb.x, p);
        p = fmaf(fa.y, fb.y, p);
    }
    p += __shfl_down_sync(0xffffffffu, p, 2, 4);
    p += __shfl_down_sync(0xffffffffu, p, 1, 4);
    if (valid && t == 0) out[e] = p;
}

// ---------------- launch ----------------
extern "C" void kernel_launch(void* const* d_in, const int* in_sizes, int n_in,
                              void* d_out, int out_size) {
    const float* x  = (const float*)d_in[0];
    const float* W1 = (const float*)d_in[1];
    const float* b1 = (const float*)d_in[2];
    const float* W2 = (const float*)d_in[3];
    const float* b2 = (const float*)d_in[4];
    const int*   ei = (const int*)d_in[5];
    const int*   de = (const int*)d_in[6];

    int N  = in_sizes[0] / IN_C;
    int E  = in_sizes[5] / 2;
    int Ed = in_sizes[6] / 2;
    const int* src = ei;
    const int* dst = ei + E;
    float* out = (float*)d_out;

    int nb = (N + 255) / 256;

    k_deg<<<(E + 255) / 256, 256>>>(dst, E);
    k_scan<<<nb, 256>>>(N);
    k_fill<<<(E + 255) / 256, 256>>>(src, dst, E);

    k_gemm1<<<(N + 127) / 128, 256>>>(x, W1, N);

    k_gather1_layer2<<<(N + 15) / 16, 256>>>(b1, W2, N);
    k_gather2<<<(N + 31) / 32, 256>>>(b2, N);

    long long thd = (long long)Ed * 4;
    k_decode<<<(unsigned)((thd + 255) / 256), 256>>>(de, Ed, out, N);
}

// round 10
// speedup vs baseline: 2.0072x; 1.1265x over previous
#include <cuda_runtime.h>
#include <cuda_fp16.h>

#define N_NODES_MAX 50000
#define IN_C  128
#define HID_C 64
#define OUT_C 32

// ---------------- scratch (no allocations allowed) ----------------
// g_deg counts IN-EDGES only (self loop handled as +1 at use sites).
// Zero-initialized at module load; re-zeroed by k_decode at the end of every
// launch, so every execution starts from deg==0.
__device__ int   g_deg [N_NODES_MAX];
__device__ int   g_rowstart[N_NODES_MAX];
__device__ int   g_cur [N_NODES_MAX];
__device__ float g_dinv[N_NODES_MAX];
__device__ int   g_esrc[1600000];                              // CSR src lists (cap 2x E)
__device__ __align__(16) __half g_xw1h[N_NODES_MAX * HID_C];   // x @ W1 (fp16 storage)
__device__ __align__(16) float  g_hw2 [N_NODES_MAX * OUT_C];   // relu(h) @ W2
__device__ __align__(16) __half g_z16 [N_NODES_MAX * OUT_C];   // z (fp16, decode only)

// ---------------- degree histogram (in-edges) ----------------
__global__ void k_deg(const int* __restrict__ dst, int E) {
    int e = blockIdx.x * blockDim.x + threadIdx.x;
    if (e < E) atomicAdd(&g_deg[dst[e]], 1);
}

// ---------------- single-kernel scan: rowstart = exclusive-prefix(deg) ----------------
__global__ __launch_bounds__(256) void k_scan(int n) {
    __shared__ int swarp[8];
    __shared__ int soff[8];
    int bid = blockIdx.x;
    int tid = threadIdx.x;
    int lane = tid & 31, warp = tid >> 5;

    // block offset = sum deg[0 .. bid*256)
    int limit = bid * 256;
    int s = 0;
    for (int j = tid; j < limit; j += 256) s += g_deg[j];
#pragma unroll
    for (int o = 16; o > 0; o >>= 1) s += __shfl_down_sync(0xffffffffu, s, o);
    if (lane == 0) soff[warp] = s;
    __syncthreads();
    if (tid < 8) {
        int t = soff[tid];
#pragma unroll
        for (int o = 4; o > 0; o >>= 1) t += __shfl_down_sync(0xffu, t, o);
        if (tid == 0) soff[0] = t;
    }
    __syncthreads();
    int off = soff[0];

    int i = bid * 256 + tid;
    int deg = (i < n) ? g_deg[i] : 0;
    int incl = deg;
#pragma unroll
    for (int o = 1; o < 32; o <<= 1) {
        int t = __shfl_up_sync(0xffffffffu, incl, o);
        if (lane >= o) incl += t;
    }
    if (lane == 31) swarp[warp] = incl;
    __syncthreads();
    if (tid < 8) {
        int t = swarp[tid];
        int si = t;
#pragma unroll
        for (int o = 1; o < 8; o <<= 1) {
            int u = __shfl_up_sync(0xffu, si, o);
            if (tid >= o) si += u;
        }
        swarp[tid] = si - t;   // exclusive warp offsets
    }
    __syncthreads();
    if (i < n) {
        int rs = off + swarp[warp] + (incl - deg);
        g_rowstart[i] = rs;
        g_cur[i] = rs;
        g_dinv[i] = rsqrtf((float)(deg + 1));
    }
}
__global__ void k_fill(const int* __restrict__ src, const int* __restrict__ dst, int E) {
    int e = blockIdx.x * blockDim.x + threadIdx.x;
    if (e < E) {
        int pos = atomicAdd(&g_cur[dst[e]], 1);
        g_esrc[pos] = src[e];
    }
}

// ---------------- helpers for tf32 mma ----------------
__device__ __forceinline__ unsigned int f32_to_tf32(float f) {
    unsigned int r;
    asm("cvt.rna.tf32.f32 %0, %1;" : "=r"(r) : "f"(f));
    return r;
}

// ---------------- GEMM1 (tensor core, tf32): xw1 = x@W1, fp16 store ----------------
// 128 rows x 64 cols per block, 8 warps; warp = 16 rows x 64 cols.
// KT=32 k-phases; smem holds tf32 bit patterns, ldk pad 36 (conflict-free frags).
__global__ __launch_bounds__(256) void k_gemm1(const float* __restrict__ x,
                                               const float* __restrict__ W1, int n) {
    __shared__ __align__(16) unsigned int sA[128 * 36];  // [row][k]
    __shared__ __align__(16) unsigned int sB[64 * 36];   // [col][k] (W1 transposed)

    const int tid = threadIdx.x;
    const int warp = tid >> 5, lane = tid & 31;
    const int g = lane >> 2, t = lane & 3;
    const int row0 = blockIdx.x * 128;
    const int wrow = warp * 16;

    float c[8][4];
#pragma unroll
    for (int i = 0; i < 8; i++)
#pragma unroll
        for (int j = 0; j < 4; j++) c[i][j] = 0.f;

#pragma unroll
    for (int kt = 0; kt < 4; kt++) {
        // stage x tile (128 rows x 32 k) as tf32
        {
            int r = tid >> 3, f4 = tid & 7;
#pragma unroll
            for (int p = 0; p < 4; p++, r += 32) {
                int gr = row0 + r;
                float4 v = make_float4(0.f, 0.f, 0.f, 0.f);
                if (gr < n) v = *(const float4*)(x + (size_t)gr * IN_C + kt * 32 + f4 * 4);
                unsigned int* d = sA + r * 36 + f4 * 4;
                d[0] = f32_to_tf32(v.x);
                d[1] = f32_to_tf32(v.y);
                d[2] = f32_to_tf32(v.z);
                d[3] = f32_to_tf32(v.w);
            }
        }
        // stage W1 tile transposed: sB[col][k]
        for (int i = tid; i < 32 * 64; i += 256) {
            int k = i >> 6, cc = i & 63;
            sB[cc * 36 + k] = f32_to_tf32(W1[(size_t)(kt * 32 + k) * HID_C + cc]);
        }
        __syncthreads();

#pragma unroll
        for (int ks = 0; ks < 4; ks++) {
            int kk = ks * 8;
            unsigned int a0 = sA[(wrow + g) * 36 + kk + t];
            unsigned int a1 = sA[(wrow + g + 8) * 36 + kk + t];
            unsigned int a2 = sA[(wrow + g) * 36 + kk + t + 4];
            unsigned int a3 = sA[(wrow + g + 8) * 36 + kk + t + 4];
#pragma unroll
            for (int nt = 0; nt < 8; nt++) {
                unsigned int b0 = sB[(nt * 8 + g) * 36 + kk + t];
                unsigned int b1 = sB[(nt * 8 + g) * 36 + kk + t + 4];
                asm volatile(
                    "mma.sync.aligned.m16n8k8.row.col.f32.tf32.tf32.f32 "
                    "{%0,%1,%2,%3}, {%4,%5,%6,%7}, {%8,%9}, {%0,%1,%2,%3};"
                    : "+f"(c[nt][0]), "+f"(c[nt][1]), "+f"(c[nt][2]), "+f"(c[nt][3])
                    : "r"(a0), "r"(a1), "r"(a2), "r"(a3), "r"(b0), "r"(b1));
            }
        }
        __syncthreads();
    }

    // epilogue: D[g][2t],D[g][2t+1] ; D[g+8][2t],D[g+8][2t+1] per n-tile -> fp16
    int r0 = row0 + wrow + g;
    int r1 = r0 + 8;
#pragma unroll
    for (int nt = 0; nt < 8; nt++) {
        int col = nt * 8 + 2 * t;
        if (r0 < n) {
            __half2 p = __floats2half2_rn(c[nt][0], c[nt][1]);
            *(__half2*)(g_xw1h + (size_t)r0 * HID_C + col) = p;
        }
        if (r1 < n) {
            __half2 p = __floats2half2_rn(c[nt][2], c[nt][3]);
            *(__half2*)(g_xw1h + (size_t)r1 * HID_C + col) = p;
        }
    }
}

// ---------------- fused: gather layer1 (+b1, relu) then @W2 -> g_hw2 ----------------
__global__ __launch_bounds__(256) void k_gather1_layer2(const float* __restrict__ b1,
                                                        const float* __restrict__ W2, int n) {
    __shared__ __align__(16) float sh[16 * 68];   // relu(agg1) rows, padded
    __shared__ float sW2[HID_C * OUT_C];          // sW2[k*32 + c]
    int tid = threadIdx.x;
    for (int i = tid; i < HID_C * OUT_C; i += 256) sW2[i] = W2[i];

    int grp = tid >> 4, l = tid & 15;             // node group, lane (4 dims = 8B fp16)
    int node = blockIdx.x * 16 + grp;
    if (node < n) {
        float dn = g_dinv[node];
        int beg = g_rowstart[node];
        int end = beg + g_deg[node];

        uint2 us = *(const uint2*)(g_xw1h + (size_t)node * HID_C + l * 4);
        float2 s0 = __half22float2(*(const __half2*)&us.x);
        float2 s1 = __half22float2(*(const __half2*)&us.y);
        float s = dn * dn;
        float4 bb = *(const float4*)(b1 + l * 4);
        float4 acc;
        acc.x = fmaf(s0.x, s, bb.x); acc.y = fmaf(s0.y, s, bb.y);
        acc.z = fmaf(s1.x, s, bb.z); acc.w = fmaf(s1.y, s, bb.w);

        int j = beg;
        for (; j + 1 < end; j += 2) {
            int n0 = g_esrc[j], n1 = g_esrc[j + 1];
            float w0 = g_dinv[n0] * dn, w1 = g_dinv[n1] * dn;
            uint2 u0 = *(const uint2*)(g_xw1h + (size_t)n0 * HID_C + l * 4);
            uint2 u1 = *(const uint2*)(g_xw1h + (size_t)n1 * HID_C + l * 4);
            float2 a0 = __half22float2(*(const __half2*)&u0.x);
            float2 a1 = __half22float2(*(const __half2*)&u0.y);
            float2 c0 = __half22float2(*(const __half2*)&u1.x);
            float2 c1 = __half22float2(*(const __half2*)&u1.y);
            acc.x = fmaf(a0.x, w0, acc.x); acc.y = fmaf(a0.y, w0, acc.y);
            acc.z = fmaf(a1.x, w0, acc.z); acc.w = fmaf(a1.y, w0, acc.w);
            acc.x = fmaf(c0.x, w1, acc.x); acc.y = fmaf(c0.y, w1, acc.y);
            acc.z = fmaf(c1.x, w1, acc.z); acc.w = fmaf(c1.y, w1, acc.w);
        }
        if (j < end) {
            int n0 = g_esrc[j];
            float w0 = g_dinv[n0] * dn;
            uint2 u0 = *(const uint2*)(g_xw1h + (size_t)n0 * HID_C + l * 4);
            float2 a0 = __half22float2(*(const __half2*)&u0.x);
            float2 a1 = __half22float2(*(const __half2*)&u0.y);
            acc.x = fmaf(a0.x, w0, acc.x); acc.y = fmaf(a0.y, w0, acc.y);
            acc.z = fmaf(a1.x, w0, acc.z); acc.w = fmaf(a1.y, w0, acc.w);
        }
        float* dsth = sh + grp * 68 + l * 4;
        dsth[0] = fmaxf(acc.x, 0.f);
        dsth[1] = fmaxf(acc.y, 0.f);
        dsth[2] = fmaxf(acc.z, 0.f);
        dsth[3] = fmaxf(acc.w, 0.f);
    }
    __syncthreads();

    int nd = tid >> 4, c = tid & 15;
    int gnode = blockIdx.x * 16 + nd;
    if (gnode >= n) return;
    const float* hrow = sh + nd * 68;
    float a0 = 0.f, a1 = 0.f;
#pragma unroll 8
    for (int k = 0; k < HID_C; k++) {
        float hk = hrow[k];
        a0 = fmaf(hk, sW2[k * OUT_C + c], a0);
        a1 = fmaf(hk, sW2[k * OUT_C + c + 16], a1);
    }
    g_hw2[(size_t)gnode * OUT_C + c]      = a0;
    g_hw2[(size_t)gnode * OUT_C + c + 16] = a1;
}

// ---------------- gather layer2 (+b2) -> z (fp16) ----------------
__global__ __launch_bounds__(256) void k_gather2(const float* __restrict__ b2, int n) {
    int tid = threadIdx.x;
    int grp = tid >> 3, l = tid & 7;
    int node = blockIdx.x * 32 + grp;
    if (node >= n) return;

    float dn = g_dinv[node];
    int beg = g_rowstart[node];
    int end = beg + g_deg[node];

    float4 acc = *(const float4*)(g_hw2 + (size_t)node * OUT_C + l * 4);
    float s = dn * dn;
    float4 bb = *(const float4*)(b2 + l * 4);
    acc.x = fmaf(acc.x, s, bb.x); acc.y = fmaf(acc.y, s, bb.y);
    acc.z = fmaf(acc.z, s, bb.z); acc.w = fmaf(acc.w, s, bb.w);

    int j = beg;
    for (; j + 1 < end; j += 2) {
        int s0 = g_esrc[j], s1 = g_esrc[j + 1];
        float w0 = g_dinv[s0] * dn, w1 = g_dinv[s1] * dn;
        float4 v0 = *(const float4*)(g_hw2 + (size_t)s0 * OUT_C + l * 4);
        float4 v1 = *(const float4*)(g_hw2 + (size_t)s1 * OUT_C + l * 4);
        acc.x = fmaf(v0.x, w0, acc.x); acc.y = fmaf(v0.y, w0, acc.y);
        acc.z = fmaf(v0.z, w0, acc.z); acc.w = fmaf(v0.w, w0, acc.w);
        acc.x = fmaf(v1.x, w1, acc.x); acc.y = fmaf(v1.y, w1, acc.y);
        acc.z = fmaf(v1.z, w1, acc.z); acc.w = fmaf(v1.w, w1, acc.w);
    }
    if (j < end) {
        int s0 = g_esrc[j];
        float w0 = g_dinv[s0] * dn;
        float4 v0 = *(const float4*)(g_hw2 + (size_t)s0 * OUT_C + l * 4);
        acc.x = fmaf(v0.x, w0, acc.x); acc.y = fmaf(v0.y, w0, acc.y);
        acc.z = fmaf(v0.z, w0, acc.z); acc.w = fmaf(v0.w, w0, acc.w);
    }
    __half2 p0 = __floats2half2_rn(acc.x, acc.y);
    __half2 p1 = __floats2half2_rn(acc.z, acc.w);
    uint2 u;
    u.x = *(const unsigned int*)&p0;
    u.y = *(const unsigned int*)&p1;
    *(uint2*)(g_z16 + (size_t)node * OUT_C + l * 4) = u;
}

// ---------------- decode: logits[e] = dot(z[a], z[b]) (fp16 z, fp32 math) ----------------
// Also resets g_deg to 0 for the next launch (keeps per-call state invariant).
__global__ __launch_bounds__(256) void k_decode(const int* __restrict__ de, int E,
                                                float* __restrict__ out, int n) {
    int g = blockIdx.x * blockDim.x + threadIdx.x;
    if (g < n) g_deg[g] = 0;   // restore deg==0 invariant for next call
    int e = g >> 2, t = g & 3;
    bool valid = (e < E);
    if (!valid) e = 0;
    int a = 0, b = 0;
    if (t == 0) { a = de[e]; b = de[E + e]; }
    a = __shfl_sync(0xffffffffu, a, 0, 4);
    b = __shfl_sync(0xffffffffu, b, 0, 4);
    uint4 ua = *(const uint4*)(g_z16 + (size_t)a * OUT_C + t * 8);
    uint4 ub = *(const uint4*)(g_z16 + (size_t)b * OUT_C + t * 8);
    float p = 0.f;
    const unsigned int* pa = &ua.x;
    const unsigned int* pb = &ub.x;
#pragma unroll
    for (int i = 0; i < 4; i++) {
        float2 fa = __half22float2(*(const __half2*)&pa[i]);
        float2 fb = __half22float2(*(const __half2*)&pb[i]);
        p = fmaf(fa.x, fb.x, p);
        p = fmaf(fa.y, fb.y, p);
    }
    p += __shfl_down_sync(0xffffffffu, p, 2, 4);
    p += __shfl_down_sync(0xffffffffu, p, 1, 4);
    if (valid && t == 0) out[e] = p;
}

// ---------------- launch ----------------
extern "C" void kernel_launch(void* const* d_in, const int* in_sizes, int n_in,
                              void* d_out, int out_size) {
    const float* x  = (const float*)d_in[0];
    const float* W1 = (const float*)d_in[1];
    const float* b1 = (const float*)d_in[2];
    const float* W2 = (const float*)d_in[3];
    const float* b2 = (const float*)d_in[4];
    const int*   ei = (const int*)d_in[5];
    const int*   de = (const int*)d_in[6];

    int N  = in_sizes[0] / IN_C;
    int E  = in_sizes[5] / 2;
    int Ed = in_sizes[6] / 2;
    const int* src = ei;
    const int* dst = ei + E;
    float* out = (float*)d_out;

    int nb = (N + 255) / 256;

    k_deg<<<(E + 255) / 256, 256>>>(dst, E);
    k_scan<<<nb, 256>>>(N);
    k_fill<<<(E + 255) / 256, 256>>>(src, dst, E);

    k_gemm1<<<(N + 127) / 128, 256>>>(x, W1, N);

    k_gather1_layer2<<<(N + 15) / 16, 256>>>(b1, W2, N);
    k_gather2<<<(N + 31) / 32, 256>>>(b2, N);

    long long thd = (long long)Ed * 4;
    k_decode<<<(unsigned)((thd + 255) / 256), 256>>>(de, Ed, out, N);
}